// round 8
// baseline (speedup 1.0000x reference)
#include <cuda_runtime.h>

#define NQ   12
#define DIM  4096
#define NL   5
#define NT   256
// pad-2 layout: loc(j) = j + 2*(j>>4) -> stride-18 rows, 16B-aligned rows
#define PAD_DIM (DIM + 2 * (DIM / 16))   // 4608 ull = 36 KB
#define NCTA 592                          // 148 SMs x 4 CTAs (persistent)

typedef unsigned long long ull;

__device__ __forceinline__ ull f32x2_mul(ull a, ull b) {
    ull r;
    asm("mul.rn.f32x2 %0, %1, %2;" : "=l"(r) : "l"(a), "l"(b));
    return r;
}
__device__ __forceinline__ ull f32x2_fma(ull a, ull b, ull c) {
    ull r;
    asm("fma.rn.f32x2 %0, %1, %2, %3;" : "=l"(r) : "l"(a), "l"(b), "l"(c));
    return r;
}
__device__ __forceinline__ ull swap_halves(ull v) {
    uint2 t = *reinterpret_cast<uint2*>(&v);
    uint2 s = make_uint2(t.y, t.x);
    return *reinterpret_cast<ull*>(&s);
}
__device__ __forceinline__ ull pack2(float lo, float hi) {
    uint2 t = make_uint2(__float_as_uint(lo), __float_as_uint(hi));
    return *reinterpret_cast<ull*>(&t);
}
__device__ __forceinline__ float2 cmul(float2 a, float2 b) {
    return make_float2(a.x * b.x - a.y * b.y, a.x * b.y + a.y * b.x);
}

// one pair-gate in packed form: rows given as {c,d} with c=dup(re), d=(-im,im)
__device__ __forceinline__ void pair_gate(ull& A0, ull& A1,
                                          const ulonglong2 p0, const ulonglong2 p1,
                                          const ulonglong2 p2, const ulonglong2 p3) {
    ull s0 = A0, s1 = A1;
    ull s0w = swap_halves(s0), s1w = swap_halves(s1);
    ull n0 = f32x2_mul(p0.x, s0);
    n0 = f32x2_fma(p0.y, s0w, n0);
    n0 = f32x2_fma(p1.x, s1,  n0);
    n0 = f32x2_fma(p1.y, s1w, n0);
    ull n1 = f32x2_mul(p2.x, s0);
    n1 = f32x2_fma(p2.y, s0w, n1);
    n1 = f32x2_fma(p3.x, s1,  n1);
    n1 = f32x2_fma(p3.y, s1w, n1);
    A0 = n0; A1 = n1;
}

// apply 4 gates; gate m=0's coefficient rows are passed in pre-loaded (hoisted
// above the preceding barrier), gates 1..3 load from shared.
template <int QBASE>
__device__ __forceinline__ void gates4p(ull a[16], const ulonglong2* __restrict__ U,
                                        const ulonglong2 g0[4]) {
    #pragma unroll
    for (int k = 0; k < 16; k++)
        if (!(k & 1))
            pair_gate(a[k], a[k | 1], g0[0], g0[1], g0[2], g0[3]);
    #pragma unroll
    for (int m = 1; m < 4; m++) {
        const int q = QBASE - m;
        const ulonglong2 p0 = U[q * 4 + 0];
        const ulonglong2 p1 = U[q * 4 + 1];
        const ulonglong2 p2 = U[q * 4 + 2];
        const ulonglong2 p3 = U[q * 4 + 3];
        #pragma unroll
        for (int k = 0; k < 16; k++)
            if (!(k & (1 << m)))
                pair_gate(a[k], a[k | (1 << m)], p0, p1, p2, p3);
    }
}

__device__ __forceinline__ void prefetch4(ulonglong2 g[4],
                                          const ulonglong2* __restrict__ U, int q) {
    g[0] = U[q * 4 + 0]; g[1] = U[q * 4 + 1];
    g[2] = U[q * 4 + 2]; g[3] = U[q * 4 + 3];
}

__global__ void __launch_bounds__(NT, 4)
qnet_kernel(const float* __restrict__ x,
            const float* __restrict__ iw,
            const float* __restrict__ th,
            const float* __restrict__ ow,
            float* __restrict__ out,
            int nb) {
    __shared__ __align__(16) ull st[PAD_DIM];             // 36 KB packed state
    __shared__ __align__(16) ulonglong2 Up[NL * NQ * 4];  // all layers' gates
    __shared__ float2 U00s[NQ], U10s[NQ];                 // layer-0 col-0 entries
    __shared__ float red0[NT / 32], red1[NT / 32];

    const int tid = threadIdx.x;

    // ---- CNOT-ring scatter map (inverse perm), GF(2)-linear closed form ----
    int gt = tid ^ (tid >> 1); gt ^= gt >> 2; gt ^= gt >> 4;
    const int par_t = gt & 1;
    const int F_t   = gt ^ (par_t << 11);
    const int DSTK[16] = {0x000, 0x9FF, 0xBFF, 0x200, 0xFFF, 0x600, 0x400, 0xDFF,
                          0x7FF, 0xE00, 0xC00, 0x5FF, 0x800, 0x1FF, 0x3FF, 0xA00};
    const bool S01K[16] = {0,1,1,0, 0,1,1,0, 1,0,0,1, 1,0,0,1};
    const bool S23K[16] = {0,1,0,1, 0,1,0,1, 0,1,0,1, 0,1,0,1};

    const int bB = 18 * (tid & 0xF0) + (tid & 15);   // phase B: k at bB + 18k
    const int bC = tid + 2 * (tid >> 4);             // phase C: k at bC + 288k
    ulonglong2* st128 = reinterpret_cast<ulonglong2*>(st);

    ull a[16];

    // ================= persistent loop over batch elements =================
    for (int b = blockIdx.x; b < nb; b += NCTA) {

        // ---- build ALL layers' fused gates: one thread per (layer,qubit) ----
        if (tid < NL * NQ) {
            const int l = tid / NQ, q = tid % NQ;
            float xin = tanhf(x[b * NQ + q]);
            float g  = 0.5f * iw[l * NQ + q] * xin;
            float aa = 0.5f * th[(l * NQ + q) * 2 + 0];
            float bb = 0.5f * th[(l * NQ + q) * 2 + 1];
            float sg, cg, sa, ca, sb, cb;
            __sincosf(g,  &sg, &cg);
            __sincosf(aa, &sa, &ca);
            __sincosf(bb, &sb, &cb);
            float cc = ca * cg, ss = sa * sg, sc = sa * cg, cs = ca * sg;
            float2 e0 = make_float2(cb, -sb);
            float2 e1 = make_float2(cb,  sb);
            float2 u00 = cmul(e0, make_float2(cc,   ss));
            float2 u01 = cmul(e0, make_float2(-sc, -cs));
            float2 u10 = cmul(e1, make_float2(sc,  -cs));
            float2 u11 = cmul(e1, make_float2(cc,  -ss));
            ulonglong2* Uq = Up + (l * NQ + q) * 4;
            Uq[0] = make_ulonglong2(pack2(u00.x, u00.x), pack2(-u00.y, u00.y));
            Uq[1] = make_ulonglong2(pack2(u01.x, u01.x), pack2(-u01.y, u01.y));
            Uq[2] = make_ulonglong2(pack2(u10.x, u10.x), pack2(-u10.y, u10.y));
            Uq[3] = make_ulonglong2(pack2(u11.x, u11.x), pack2(-u11.y, u11.y));
            if (l == 0) { U00s[q] = u00; U10s[q] = u10; }
        }
        __syncthreads();

        // ---------------- layer 0: product state, scatter-stored -------------
        {
            float2 plow = make_float2(1.f, 0.f);
            #pragma unroll
            for (int p = 0; p < 8; p++) {                 // tid bit p <-> qubit 11-p
                float2 row = ((tid >> p) & 1) ? U10s[11 - p] : U00s[11 - p];
                plow = cmul(plow, row);
            }
            #pragma unroll
            for (int k = 0; k < 16; k++) {                // j = (k<<8) | tid
                float2 amp = plow;
                #pragma unroll
                for (int m = 0; m < 4; m++) {             // j bit 8+m <-> qubit 3-m
                    float2 row = ((k >> m) & 1) ? U10s[3 - m] : U00s[3 - m];
                    amp = cmul(amp, row);
                }
                int d = DSTK[k] ^ F_t;
                st[d + 2 * (d >> 4)] = pack2(amp.x, amp.y);
            }
        }
        ulonglong2 gpre[4];
        prefetch4(gpre, Up + 1 * (NQ * 4), 11);   // layer-1 phase-A gate 0 (qubit 11)
        __syncthreads();

        // ---------------- layers 1..4 ----------------------------------------
        #pragma unroll 1
        for (int l = 1; l < NL; l++) {
            const ulonglong2* Ul = Up + l * (NQ * 4);

            // phase A: thread-local contiguous rows, 128-bit accesses
            #pragma unroll
            for (int q = 0; q < 8; q++) {
                ulonglong2 v = st128[9 * tid + q];
                a[2 * q] = v.x; a[2 * q + 1] = v.y;
            }
            gates4p<11>(a, Ul, gpre);             // qubits 11,10,9,8 (bits 0..3)
            #pragma unroll
            for (int q = 0; q < 8; q++)
                st128[9 * tid + q] = make_ulonglong2(a[2 * q], a[2 * q + 1]);
            __syncwarp();                         // A->B exchange intra-half-warp

            // phase B
            #pragma unroll
            for (int k = 0; k < 16; k++) a[k] = st[bB + 18 * k];
            prefetch4(gpre, Ul, 7);               // phase-B gate 0 (qubit 7)
            gates4p<7>(a, Ul, gpre);              // qubits 7,6,5,4 (bits 4..7)
            #pragma unroll
            for (int k = 0; k < 16; k++) st[bB + 18 * k] = a[k];
            prefetch4(gpre, Ul, 3);               // hoist C gate 0 above barrier
            __syncthreads();                      // B->C crosses warps

            // phase C (+ CNOT-ring scatter except last layer)
            #pragma unroll
            for (int k = 0; k < 16; k++) a[k] = st[bC + 288 * k];
            gates4p<3>(a, Ul, gpre);              // qubits 3,2,1,0 (bits 8..11)
            if (l != NL - 1) {
                #pragma unroll
                for (int k = 0; k < 16; k++) {
                    int d = DSTK[k] ^ F_t;
                    st[d + 2 * (d >> 4)] = a[k];
                }
                prefetch4(gpre, Up + (l + 1) * (NQ * 4), 11);  // next A gate 0
                __syncthreads();
            }
        }

        // ---------------- measurement fused into last phase-C registers ------
        float P0 = 0.f, P1 = 0.f, Q0 = 0.f, Q1 = 0.f;
        #pragma unroll
        for (int k = 0; k < 16; k++) {
            float2 v = *reinterpret_cast<float2*>(&a[k]);
            float pr = v.x * v.x + v.y * v.y;
            if (S01K[k]) P1 += pr; else P0 += pr;
            if (S23K[k]) Q1 += pr; else Q0 += pr;
        }
        float e01 = P0 - P1;
        if (par_t) e01 = -e01;
        float e23 = Q0 - Q1;

        #pragma unroll
        for (int off = 16; off > 0; off >>= 1) {
            e01 += __shfl_down_sync(0xffffffffu, e01, off);
            e23 += __shfl_down_sync(0xffffffffu, e23, off);
        }
        if ((tid & 31) == 0) { red0[tid >> 5] = e01; red1[tid >> 5] = e23; }
        __syncthreads();
        if (tid < 2) {
            const float* r = tid ? red1 : red0;
            float s = 0.f;
            #pragma unroll
            for (int w = 0; w < NT / 32; w++) s += r[w];
            out[b * 2 + tid] = ow[tid] * s;
        }
        __syncthreads();   // fence st/Up/red reuse for next element
    }
}

extern "C" void kernel_launch(void* const* d_in, const int* in_sizes, int n_in,
                              void* d_out, int out_size) {
    const float* x  = (const float*)d_in[0];   // (BATCH, 12)
    const float* iw = (const float*)d_in[1];   // (5, 12)
    const float* th = (const float*)d_in[2];   // (5, 12, 2)
    const float* ow = (const float*)d_in[3];   // (2,)
    float* out = (float*)d_out;                // (BATCH, 2)
    int batch = in_sizes[0] / NQ;
    int grid  = batch < NCTA ? batch : NCTA;
    qnet_kernel<<<grid, NT>>>(x, iw, th, ow, out, batch);
}

// round 9
// speedup vs baseline: 1.0289x; 1.0289x over previous
#include <cuda_runtime.h>

#define NQ   12
#define DIM  4096
#define NL   5
#define NT   256
// pad-2 layout: loc(j) = j + 2*(j>>4) -> stride-18 rows, 16B-aligned rows
#define PAD_DIM (DIM + 2 * (DIM / 16))   // 4608 ull = 36 KB

typedef unsigned long long ull;

__device__ __forceinline__ ull f32x2_mul(ull a, ull b) {
    ull r;
    asm("mul.rn.f32x2 %0, %1, %2;" : "=l"(r) : "l"(a), "l"(b));
    return r;
}
__device__ __forceinline__ ull f32x2_fma(ull a, ull b, ull c) {
    ull r;
    asm("fma.rn.f32x2 %0, %1, %2, %3;" : "=l"(r) : "l"(a), "l"(b), "l"(c));
    return r;
}
__device__ __forceinline__ ull swap_halves(ull v) {
    uint2 t = *reinterpret_cast<uint2*>(&v);
    uint2 s = make_uint2(t.y, t.x);
    return *reinterpret_cast<ull*>(&s);
}
__device__ __forceinline__ ull pack2(float lo, float hi) {
    uint2 t = make_uint2(__float_as_uint(lo), __float_as_uint(hi));
    return *reinterpret_cast<ull*>(&t);
}
__device__ __forceinline__ float2 cmul(float2 a, float2 b) {
    return make_float2(a.x * b.x - a.y * b.y, a.x * b.y + a.y * b.x);
}

// one pair-gate in packed form: rows given as {c,d} with c=dup(re), d=(-im,im)
__device__ __forceinline__ void pair_gate(ull& A0, ull& A1,
                                          const ulonglong2 p0, const ulonglong2 p1,
                                          const ulonglong2 p2, const ulonglong2 p3) {
    ull s0 = A0, s1 = A1;
    ull s0w = swap_halves(s0), s1w = swap_halves(s1);
    ull n0 = f32x2_mul(p0.x, s0);
    n0 = f32x2_fma(p0.y, s0w, n0);
    n0 = f32x2_fma(p1.x, s1,  n0);
    n0 = f32x2_fma(p1.y, s1w, n0);
    ull n1 = f32x2_mul(p2.x, s0);
    n1 = f32x2_fma(p2.y, s0w, n1);
    n1 = f32x2_fma(p3.x, s1,  n1);
    n1 = f32x2_fma(p3.y, s1w, n1);
    A0 = n0; A1 = n1;
}

// apply 4 gates; gate m=0's coefficient rows arrive pre-loaded in registers
// (hoisted above the preceding barrier); gates 1..3 load from shared.
template <int QBASE>
__device__ __forceinline__ void gates4p(ull a[16], const ulonglong2* __restrict__ U,
                                        const ulonglong2 g0[4]) {
    #pragma unroll
    for (int k = 0; k < 16; k += 2)
        pair_gate(a[k], a[k + 1], g0[0], g0[1], g0[2], g0[3]);
    #pragma unroll
    for (int m = 1; m < 4; m++) {
        const int q = QBASE - m;
        const ulonglong2 p0 = U[q * 4 + 0];
        const ulonglong2 p1 = U[q * 4 + 1];
        const ulonglong2 p2 = U[q * 4 + 2];
        const ulonglong2 p3 = U[q * 4 + 3];
        #pragma unroll
        for (int k = 0; k < 16; k++)
            if (!(k & (1 << m)))
                pair_gate(a[k], a[k | (1 << m)], p0, p1, p2, p3);
    }
}

__device__ __forceinline__ void prefetch4(ulonglong2 g[4],
                                          const ulonglong2* __restrict__ U, int q) {
    g[0] = U[q * 4 + 0]; g[1] = U[q * 4 + 1];
    g[2] = U[q * 4 + 2]; g[3] = U[q * 4 + 3];
}

__global__ void __launch_bounds__(NT, 4)
qnet_kernel(const float* __restrict__ x,
            const float* __restrict__ iw,
            const float* __restrict__ th,
            const float* __restrict__ ow,
            float* __restrict__ out) {
    __shared__ __align__(16) ull st[PAD_DIM];             // 36 KB packed state
    __shared__ __align__(16) ulonglong2 Up[NL * NQ * 4];  // all layers' gates
    __shared__ float2 U00s[NQ], U10s[NQ];                 // layer-0 col-0 entries
    __shared__ float red0[NT / 32], red1[NT / 32];

    const int b   = blockIdx.x;
    const int tid = threadIdx.x;

    // ---- build ALL layers' fused gates up front: one thread per (layer,qubit) ----
    if (tid < NL * NQ) {
        const int l = tid / NQ, q = tid % NQ;
        float xin = tanhf(x[b * NQ + q]);
        float g  = 0.5f * iw[l * NQ + q] * xin;
        float aa = 0.5f * th[(l * NQ + q) * 2 + 0];
        float bb = 0.5f * th[(l * NQ + q) * 2 + 1];
        float sg, cg, sa, ca, sb, cb;
        __sincosf(g,  &sg, &cg);
        __sincosf(aa, &sa, &ca);
        __sincosf(bb, &sb, &cb);
        float cc = ca * cg, ss = sa * sg, sc = sa * cg, cs = ca * sg;
        float2 e0 = make_float2(cb, -sb);
        float2 e1 = make_float2(cb,  sb);
        float2 u00 = cmul(e0, make_float2(cc,   ss));
        float2 u01 = cmul(e0, make_float2(-sc, -cs));
        float2 u10 = cmul(e1, make_float2(sc,  -cs));
        float2 u11 = cmul(e1, make_float2(cc,  -ss));
        ulonglong2* Uq = Up + (l * NQ + q) * 4;
        Uq[0] = make_ulonglong2(pack2(u00.x, u00.x), pack2(-u00.y, u00.y));
        Uq[1] = make_ulonglong2(pack2(u01.x, u01.x), pack2(-u01.y, u01.y));
        Uq[2] = make_ulonglong2(pack2(u10.x, u10.x), pack2(-u10.y, u10.y));
        Uq[3] = make_ulonglong2(pack2(u11.x, u11.x), pack2(-u11.y, u11.y));
        if (l == 0) { U00s[q] = u00; U10s[q] = u10; }
    }

    // ---- CNOT-ring scatter map (inverse perm), GF(2)-linear closed form ----
    int gt = tid ^ (tid >> 1); gt ^= gt >> 2; gt ^= gt >> 4;
    const int par_t = gt & 1;
    const int F_t   = gt ^ (par_t << 11);
    const int DSTK[16] = {0x000, 0x9FF, 0xBFF, 0x200, 0xFFF, 0x600, 0x400, 0xDFF,
                          0x7FF, 0xE00, 0xC00, 0x5FF, 0x800, 0x1FF, 0x3FF, 0xA00};
    const bool S01K[16] = {0,1,1,0, 0,1,1,0, 1,0,0,1, 1,0,0,1};
    const bool S23K[16] = {0,1,0,1, 0,1,0,1, 0,1,0,1, 0,1,0,1};

    const int bB = 18 * (tid & 0xF0) + (tid & 15);   // phase B: k at bB + 18k
    const int bC = tid + 2 * (tid >> 4);             // phase C: k at bC + 288k
    ulonglong2* st128 = reinterpret_cast<ulonglong2*>(st);

    ull a[16];
    __syncthreads();

    // ---------------- layer 0: product state, scatter-stored (post-perm) -------
    {
        float2 plow = make_float2(1.f, 0.f);
        #pragma unroll
        for (int p = 0; p < 8; p++) {                 // tid bit p <-> qubit 11-p
            float2 row = ((tid >> p) & 1) ? U10s[11 - p] : U00s[11 - p];
            plow = cmul(plow, row);
        }
        #pragma unroll
        for (int k = 0; k < 16; k++) {                // j = (k<<8) | tid
            float2 amp = plow;
            #pragma unroll
            for (int m = 0; m < 4; m++) {             // j bit 8+m <-> qubit 3-m
                float2 row = ((k >> m) & 1) ? U10s[3 - m] : U00s[3 - m];
                amp = cmul(amp, row);
            }
            int d = DSTK[k] ^ F_t;
            st[d + 2 * (d >> 4)] = pack2(amp.x, amp.y);
        }
    }
    ulonglong2 gpre[4];
    prefetch4(gpre, Up + 1 * (NQ * 4), 11);   // hoist layer-1 phase-A gate 0
    __syncthreads();

    // ---------------- layers 1..4 ---------------------------------------------
    #pragma unroll 1
    for (int l = 1; l < NL; l++) {
        const ulonglong2* Ul = Up + l * (NQ * 4);

        // phase A: thread-local contiguous rows, 128-bit accesses
        #pragma unroll
        for (int q = 0; q < 8; q++) {
            ulonglong2 v = st128[9 * tid + q];
            a[2 * q] = v.x; a[2 * q + 1] = v.y;
        }
        gates4p<11>(a, Ul, gpre);                 // qubits 11,10,9,8 (bits 0..3)
        #pragma unroll
        for (int q = 0; q < 8; q++)
            st128[9 * tid + q] = make_ulonglong2(a[2 * q], a[2 * q + 1]);
        prefetch4(gpre, Ul, 7);                   // hoist phase-B gate 0
        __syncwarp();                             // A->B exchange intra-half-warp

        // phase B
        #pragma unroll
        for (int k = 0; k < 16; k++) a[k] = st[bB + 18 * k];
        gates4p<7>(a, Ul, gpre);                  // qubits 7,6,5,4 (bits 4..7)
        #pragma unroll
        for (int k = 0; k < 16; k++) st[bB + 18 * k] = a[k];
        prefetch4(gpre, Ul, 3);                   // hoist phase-C gate 0
        __syncthreads();                          // B->C crosses warps

        // phase C (+ CNOT-ring scatter except last layer)
        #pragma unroll
        for (int k = 0; k < 16; k++) a[k] = st[bC + 288 * k];
        gates4p<3>(a, Ul, gpre);                  // qubits 3,2,1,0 (bits 8..11)
        if (l != NL - 1) {
            #pragma unroll
            for (int k = 0; k < 16; k++) {
                int d = DSTK[k] ^ F_t;
                st[d + 2 * (d >> 4)] = a[k];
            }
            prefetch4(gpre, Up + (l + 1) * (NQ * 4), 11);  // hoist next A gate 0
            __syncthreads();
        }
    }

    // ---------------- measurement fused into last phase-C registers ------------
    float P0 = 0.f, P1 = 0.f, Q0 = 0.f, Q1 = 0.f;
    #pragma unroll
    for (int k = 0; k < 16; k++) {
        float2 v = *reinterpret_cast<float2*>(&a[k]);
        float pr = v.x * v.x + v.y * v.y;
        if (S01K[k]) P1 += pr; else P0 += pr;
        if (S23K[k]) Q1 += pr; else Q0 += pr;
    }
    float e01 = P0 - P1;
    if (par_t) e01 = -e01;
    float e23 = Q0 - Q1;

    #pragma unroll
    for (int off = 16; off > 0; off >>= 1) {
        e01 += __shfl_down_sync(0xffffffffu, e01, off);
        e23 += __shfl_down_sync(0xffffffffu, e23, off);
    }
    if ((tid & 31) == 0) { red0[tid >> 5] = e01; red1[tid >> 5] = e23; }
    __syncthreads();
    if (tid < 2) {
        const float* r = tid ? red1 : red0;
        float s = 0.f;
        #pragma unroll
        for (int w = 0; w < NT / 32; w++) s += r[w];
        out[b * 2 + tid] = ow[tid] * s;
    }
}

extern "C" void kernel_launch(void* const* d_in, const int* in_sizes, int n_in,
                              void* d_out, int out_size) {
    const float* x  = (const float*)d_in[0];   // (BATCH, 12)
    const float* iw = (const float*)d_in[1];   // (5, 12)
    const float* th = (const float*)d_in[2];   // (5, 12, 2)
    const float* ow = (const float*)d_in[3];   // (2,)
    float* out = (float*)d_out;                // (BATCH, 2)
    int batch = in_sizes[0] / NQ;
    qnet_kernel<<<batch, NT>>>(x, iw, th, ow, out);
}

// round 10
// speedup vs baseline: 1.1281x; 1.0964x over previous
#include <cuda_runtime.h>

#define NQ   12
#define DIM  4096
#define NL   5
#define NT   256
// pad-2 layout: loc(j) = j + 2*(j>>4) -> stride-18 rows, 16B-aligned rows
#define PAD_DIM (DIM + 2 * (DIM / 16))   // 4608 ull = 36 KB

typedef unsigned long long ull;

__device__ __forceinline__ ull f32x2_mul(ull a, ull b) {
    ull r;
    asm("mul.rn.f32x2 %0, %1, %2;" : "=l"(r) : "l"(a), "l"(b));
    return r;
}
__device__ __forceinline__ ull f32x2_fma(ull a, ull b, ull c) {
    ull r;
    asm("fma.rn.f32x2 %0, %1, %2, %3;" : "=l"(r) : "l"(a), "l"(b), "l"(c));
    return r;
}
__device__ __forceinline__ ull swap_halves(ull v) {
    uint2 t = *reinterpret_cast<uint2*>(&v);
    uint2 s = make_uint2(t.y, t.x);
    return *reinterpret_cast<ull*>(&s);
}
__device__ __forceinline__ ull pack2(float lo, float hi) {
    uint2 t = make_uint2(__float_as_uint(lo), __float_as_uint(hi));
    return *reinterpret_cast<ull*>(&t);
}
__device__ __forceinline__ float2 cmul(float2 a, float2 b) {
    return make_float2(a.x * b.x - a.y * b.y, a.x * b.y + a.y * b.x);
}

// apply 4 gates: register-nibble bit m (pair stride 1<<m) <-> qubit QBASE - m
// U layout per qubit q: 4 x ulonglong2 = {c00,d00},{c01,d01},{c10,d10},{c11,d11}
template <int QBASE>
__device__ __forceinline__ void gates4p(ull a[16], const ulonglong2* __restrict__ U) {
    #pragma unroll
    for (int m = 0; m < 4; m++) {
        const int q = QBASE - m;
        const ulonglong2 p0 = U[q * 4 + 0];
        const ulonglong2 p1 = U[q * 4 + 1];
        const ulonglong2 p2 = U[q * 4 + 2];
        const ulonglong2 p3 = U[q * 4 + 3];
        #pragma unroll
        for (int k = 0; k < 16; k++) {
            if (!(k & (1 << m))) {
                ull s0 = a[k], s1 = a[k | (1 << m)];
                ull s0w = swap_halves(s0), s1w = swap_halves(s1);
                ull n0 = f32x2_mul(p0.x, s0);
                n0 = f32x2_fma(p0.y, s0w, n0);
                n0 = f32x2_fma(p1.x, s1,  n0);
                n0 = f32x2_fma(p1.y, s1w, n0);
                ull n1 = f32x2_mul(p2.x, s0);
                n1 = f32x2_fma(p2.y, s0w, n1);
                n1 = f32x2_fma(p3.x, s1,  n1);
                n1 = f32x2_fma(p3.y, s1w, n1);
                a[k] = n0; a[k | (1 << m)] = n1;
            }
        }
    }
}

// fused gate angles -> full 2x2 complex matrix entries
__device__ __forceinline__ void fuse_gate(float g, float aa, float bb,
                                          float2& u00, float2& u01,
                                          float2& u10, float2& u11) {
    float sg, cg, sa, ca, sb, cb;
    __sincosf(g,  &sg, &cg);
    __sincosf(aa, &sa, &ca);
    __sincosf(bb, &sb, &cb);
    float cc = ca * cg, ss = sa * sg, sc = sa * cg, cs = ca * sg;
    float2 e0 = make_float2(cb, -sb);
    float2 e1 = make_float2(cb,  sb);
    u00 = cmul(e0, make_float2(cc,   ss));
    u01 = cmul(e0, make_float2(-sc, -cs));
    u10 = cmul(e1, make_float2(sc,  -cs));
    u11 = cmul(e1, make_float2(cc,  -ss));
}

__global__ void __launch_bounds__(NT, 4)
qnet_kernel(const float* __restrict__ x,
            const float* __restrict__ iw,
            const float* __restrict__ th,
            const float* __restrict__ ow,
            float* __restrict__ out) {
    __shared__ __align__(16) ull st[PAD_DIM];             // 36 KB packed state
    __shared__ __align__(16) ulonglong2 Up[NL * NQ * 4];  // layers 1..4 gates
    __shared__ float2 U00s[NQ], U10s[NQ];                 // layer-0 col-0 entries
    __shared__ float red0[NT / 32], red1[NT / 32];

    const int b   = blockIdx.x;
    const int tid = threadIdx.x;

    // ---- stage 1: build ONLY layer-0 column-0 entries (12 threads) ----------
    if (tid < NQ) {
        float xin = tanhf(x[b * NQ + tid]);
        float g  = 0.5f * iw[tid] * xin;
        float aa = 0.5f * th[tid * 2 + 0];
        float bb = 0.5f * th[tid * 2 + 1];
        float2 u00, u01, u10, u11;
        fuse_gate(g, aa, bb, u00, u01, u10, u11);
        U00s[tid] = u00;
        U10s[tid] = u10;
    }

    // ---- CNOT-ring scatter map (inverse perm), GF(2)-linear closed form ----
    int gt = tid ^ (tid >> 1); gt ^= gt >> 2; gt ^= gt >> 4;
    const int par_t = gt & 1;
    const int F_t   = gt ^ (par_t << 11);
    const int DSTK[16] = {0x000, 0x9FF, 0xBFF, 0x200, 0xFFF, 0x600, 0x400, 0xDFF,
                          0x7FF, 0xE00, 0xC00, 0x5FF, 0x800, 0x1FF, 0x3FF, 0xA00};
    const bool S01K[16] = {0,1,1,0, 0,1,1,0, 1,0,0,1, 1,0,0,1};
    const bool S23K[16] = {0,1,0,1, 0,1,0,1, 0,1,0,1, 0,1,0,1};

    const int bB = 18 * (tid & 0xF0) + (tid & 15);   // phase B: k at bB + 18k
    const int bC = tid + 2 * (tid >> 4);             // phase C: k at bC + 288k
    ulonglong2* st128 = reinterpret_cast<ulonglong2*>(st);

    ull a[16];
    __syncthreads();

    // ---- stage 2: layers 1..4 gate build (48 threads) OVERLAPPED with the ----
    // ---- layer-0 product-state compute done by all threads                ----
    if (tid < (NL - 1) * NQ) {
        const int l = 1 + tid / NQ, q = tid % NQ;
        float xin = tanhf(x[b * NQ + q]);
        float g  = 0.5f * iw[l * NQ + q] * xin;
        float aa = 0.5f * th[(l * NQ + q) * 2 + 0];
        float bb = 0.5f * th[(l * NQ + q) * 2 + 1];
        float2 u00, u01, u10, u11;
        fuse_gate(g, aa, bb, u00, u01, u10, u11);
        ulonglong2* Uq = Up + (l * NQ + q) * 4;
        Uq[0] = make_ulonglong2(pack2(u00.x, u00.x), pack2(-u00.y, u00.y));
        Uq[1] = make_ulonglong2(pack2(u01.x, u01.x), pack2(-u01.y, u01.y));
        Uq[2] = make_ulonglong2(pack2(u10.x, u10.x), pack2(-u10.y, u10.y));
        Uq[3] = make_ulonglong2(pack2(u11.x, u11.x), pack2(-u11.y, u11.y));
    }

    // layer 0: |0..0> -> product state, scatter-stored (post-perm layout)
    {
        float2 plow = make_float2(1.f, 0.f);
        #pragma unroll
        for (int p = 0; p < 8; p++) {                 // tid bit p <-> qubit 11-p
            float2 row = ((tid >> p) & 1) ? U10s[11 - p] : U00s[11 - p];
            plow = cmul(plow, row);
        }
        #pragma unroll
        for (int k = 0; k < 16; k++) {                // j = (k<<8) | tid
            float2 amp = plow;
            #pragma unroll
            for (int m = 0; m < 4; m++) {             // j bit 8+m <-> qubit 3-m
                float2 row = ((k >> m) & 1) ? U10s[3 - m] : U00s[3 - m];
                amp = cmul(amp, row);
            }
            int d = DSTK[k] ^ F_t;
            st[d + 2 * (d >> 4)] = pack2(amp.x, amp.y);
        }
    }
    __syncthreads();

    // ---------------- layers 1..4 ---------------------------------------------
    #pragma unroll 1
    for (int l = 1; l < NL; l++) {
        const ulonglong2* Ul = Up + l * (NQ * 4);

        // phase A: thread-local contiguous rows, 128-bit accesses
        #pragma unroll
        for (int q = 0; q < 8; q++) {
            ulonglong2 v = st128[9 * tid + q];
            a[2 * q] = v.x; a[2 * q + 1] = v.y;
        }
        gates4p<11>(a, Ul);                       // qubits 11,10,9,8 (bits 0..3)
        #pragma unroll
        for (int q = 0; q < 8; q++)
            st128[9 * tid + q] = make_ulonglong2(a[2 * q], a[2 * q + 1]);
        __syncwarp();                             // A->B exchange intra-half-warp

        // phase B
        #pragma unroll
        for (int k = 0; k < 16; k++) a[k] = st[bB + 18 * k];
        gates4p<7>(a, Ul);                        // qubits 7,6,5,4 (bits 4..7)
        #pragma unroll
        for (int k = 0; k < 16; k++) st[bB + 18 * k] = a[k];
        __syncthreads();                          // B->C crosses warps

        // phase C (+ CNOT-ring scatter except last layer)
        #pragma unroll
        for (int k = 0; k < 16; k++) a[k] = st[bC + 288 * k];
        gates4p<3>(a, Ul);                        // qubits 3,2,1,0 (bits 8..11)
        if (l != NL - 1) {
            #pragma unroll
            for (int k = 0; k < 16; k++) {
                int d = DSTK[k] ^ F_t;
                st[d + 2 * (d >> 4)] = a[k];
            }
            __syncthreads();
        }
    }

    // ---------------- measurement fused into last phase-C registers ------------
    float P0 = 0.f, P1 = 0.f, Q0 = 0.f, Q1 = 0.f;
    #pragma unroll
    for (int k = 0; k < 16; k++) {
        float2 v = *reinterpret_cast<float2*>(&a[k]);
        float pr = v.x * v.x + v.y * v.y;
        if (S01K[k]) P1 += pr; else P0 += pr;
        if (S23K[k]) Q1 += pr; else Q0 += pr;
    }
    float e01 = P0 - P1;
    if (par_t) e01 = -e01;
    float e23 = Q0 - Q1;

    #pragma unroll
    for (int off = 16; off > 0; off >>= 1) {
        e01 += __shfl_down_sync(0xffffffffu, e01, off);
        e23 += __shfl_down_sync(0xffffffffu, e23, off);
    }
    if ((tid & 31) == 0) { red0[tid >> 5] = e01; red1[tid >> 5] = e23; }
    __syncthreads();
    if (tid < 2) {
        const float* r = tid ? red1 : red0;
        float s = 0.f;
        #pragma unroll
        for (int w = 0; w < NT / 32; w++) s += r[w];
        out[b * 2 + tid] = ow[tid] * s;
    }
}

extern "C" void kernel_launch(void* const* d_in, const int* in_sizes, int n_in,
                              void* d_out, int out_size) {
    const float* x  = (const float*)d_in[0];   // (BATCH, 12)
    const float* iw = (const float*)d_in[1];   // (5, 12)
    const float* th = (const float*)d_in[2];   // (5, 12, 2)
    const float* ow = (const float*)d_in[3];   // (2,)
    float* out = (float*)d_out;                // (BATCH, 2)
    int batch = in_sizes[0] / NQ;
    qnet_kernel<<<batch, NT>>>(x, iw, th, ow, out);
}

// round 11
// speedup vs baseline: 1.2267x; 1.0873x over previous
#include <cuda_runtime.h>

#define NQ   12
#define DIM  4096
#define NL   5
#define NT   256
// pad-2 layout: loc(j) = j + 2*(j>>4) -> stride-18 rows, 16B-aligned rows
#define PAD_DIM (DIM + 2 * (DIM / 16))   // 4608 ull = 36 KB

typedef unsigned long long ull;

__device__ __forceinline__ ull f32x2_mul(ull a, ull b) {
    ull r;
    asm("mul.rn.f32x2 %0, %1, %2;" : "=l"(r) : "l"(a), "l"(b));
    return r;
}
__device__ __forceinline__ ull f32x2_fma(ull a, ull b, ull c) {
    ull r;
    asm("fma.rn.f32x2 %0, %1, %2, %3;" : "=l"(r) : "l"(a), "l"(b), "l"(c));
    return r;
}
__device__ __forceinline__ ull swap_halves(ull v) {
    uint2 t = *reinterpret_cast<uint2*>(&v);
    uint2 s = make_uint2(t.y, t.x);
    return *reinterpret_cast<ull*>(&s);
}
__device__ __forceinline__ ull pack2(float lo, float hi) {
    uint2 t = make_uint2(__float_as_uint(lo), __float_as_uint(hi));
    return *reinterpret_cast<ull*>(&t);
}
__device__ __forceinline__ float2 cmul(float2 a, float2 b) {
    return make_float2(a.x * b.x - a.y * b.y, a.x * b.y + a.y * b.x);
}

// Euler phase: a[16] <- D1 * (R3..R0) * (D2 * a), all tables packed-dup form.
// rotation m acts on pairs (k, k^(1<<m)) for qubit QBASE-m; real coefficients.
template <int QBASE>
__device__ __forceinline__ void phase_euler(ull a[16],
                                            const ull* __restrict__ rotL,
                                            const ulonglong2* __restrict__ d2,
                                            const ulonglong2* __restrict__ d1) {
    #pragma unroll
    for (int k = 0; k < 16; k++) {
        ulonglong2 t = d2[k];
        ull r = f32x2_mul(t.x, a[k]);
        a[k] = f32x2_fma(t.y, swap_halves(a[k]), r);
    }
    #pragma unroll
    for (int m = 0; m < 4; m++) {
        const int qq = QBASE - m;
        const ull c  = rotL[qq * 3 + 0];
        const ull s  = rotL[qq * 3 + 1];
        const ull ns = rotL[qq * 3 + 2];
        #pragma unroll
        for (int k = 0; k < 16; k++) {
            if (!(k & (1 << m))) {
                ull s0 = a[k], s1 = a[k | (1 << m)];
                ull n0 = f32x2_mul(c, s0);
                n0 = f32x2_fma(ns, s1, n0);
                ull n1 = f32x2_mul(s, s0);
                n1 = f32x2_fma(c,  s1, n1);
                a[k] = n0; a[k | (1 << m)] = n1;
            }
        }
    }
    #pragma unroll
    for (int k = 0; k < 16; k++) {
        ulonglong2 t = d1[k];
        ull r = f32x2_mul(t.x, a[k]);
        a[k] = f32x2_fma(t.y, swap_halves(a[k]), r);
    }
}

// fused gate angles -> full 2x2 complex matrix entries (U = RZ(b)RY(a)RX(g))
__device__ __forceinline__ void fuse_gate(float g, float aa, float bb,
                                          float2& u00, float2& u01,
                                          float2& u10, float2& u11) {
    float sg, cg, sa, ca, sb, cb;
    __sincosf(g,  &sg, &cg);
    __sincosf(aa, &sa, &ca);
    __sincosf(bb, &sb, &cb);
    float cc = ca * cg, ss = sa * sg, sc = sa * cg, cs = ca * sg;
    float2 e0 = make_float2(cb, -sb);
    float2 e1 = make_float2(cb,  sb);
    u00 = cmul(e0, make_float2(cc,   ss));
    u01 = cmul(e0, make_float2(-sc, -cs));
    u10 = cmul(e1, make_float2(sc,  -cs));
    u11 = cmul(e1, make_float2(cc,  -ss));
}

__global__ void __launch_bounds__(NT, 4)
qnet_kernel(const float* __restrict__ x,
            const float* __restrict__ iw,
            const float* __restrict__ th,
            const float* __restrict__ ow,
            float* __restrict__ out) {
    __shared__ __align__(16) ull st[PAD_DIM];                 // 36 KB packed state
    __shared__ __align__(16) ulonglong2 d2tab[(NL - 1) * 3 * 16];  // 3 KB
    __shared__ __align__(16) ulonglong2 d1tab[(NL - 1) * 3 * 16];  // 3 KB
    __shared__ ull rot[(NL - 1) * NQ * 3];                    // packed c, s, -s
    __shared__ float2 Za[(NL - 1) * NQ], Zb[(NL - 1) * NQ];   // e^{ip}, e^{iq}
    __shared__ float2 U00s[NQ], U10s[NQ];                     // layer-0 col-0
    __shared__ float red0[NT / 32], red1[NT / 32];

    const int b   = blockIdx.x;
    const int tid = threadIdx.x;

    // ---- stage 1: per-gate build + SU(2) Euler decomposition (60 threads) ----
    if (tid < NL * NQ) {
        const int l = tid / NQ, q = tid % NQ;
        float xin = tanhf(x[b * NQ + q]);
        float g  = 0.5f * iw[l * NQ + q] * xin;
        float aa = 0.5f * th[(l * NQ + q) * 2 + 0];
        float bb = 0.5f * th[(l * NQ + q) * 2 + 1];
        float2 u00, u01, u10, u11;
        fuse_gate(g, aa, bb, u00, u01, u10, u11);
        if (l == 0) {
            U00s[q] = u00;
            U10s[q] = u10;
        } else {
            // U = D(2p) * R * D(2q2): cos = |u00|, sin = |u10|,
            // p = ( -arg(u00) + arg(u10) ) / 2, q2 = ( -arg(u00) - arg(u10) ) / 2
            float tc = sqrtf(u00.x * u00.x + u00.y * u00.y);
            float ts = sqrtf(u10.x * u10.x + u10.y * u10.y);
            float A_ = -atan2f(u00.y, u00.x);
            float B_ =  atan2f(u10.y, u10.x);
            float p  = 0.5f * (A_ + B_);
            float q2 = 0.5f * (A_ - B_);
            const int gi = (l - 1) * NQ + q;
            rot[gi * 3 + 0] = pack2(tc, tc);
            rot[gi * 3 + 1] = pack2(ts, ts);
            rot[gi * 3 + 2] = pack2(-ts, -ts);
            float sp, cp, sq, cq;
            __sincosf(p,  &sp, &cp);
            __sincosf(q2, &sq, &cq);
            Za[gi] = make_float2(cp, sp);   // bit=1 entry; bit=0 is conj
            Zb[gi] = make_float2(cq, sq);
        }
    }

    // ---- CNOT-ring scatter map (inverse perm), GF(2)-linear closed form ----
    int gt = tid ^ (tid >> 1); gt ^= gt >> 2; gt ^= gt >> 4;
    const int par_t = gt & 1;
    const int F_t   = gt ^ (par_t << 11);
    const int DSTK[16] = {0x000, 0x9FF, 0xBFF, 0x200, 0xFFF, 0x600, 0x400, 0xDFF,
                          0x7FF, 0xE00, 0xC00, 0x5FF, 0x800, 0x1FF, 0x3FF, 0xA00};
    const bool S01K[16] = {0,1,1,0, 0,1,1,0, 1,0,0,1, 1,0,0,1};
    const bool S23K[16] = {0,1,0,1, 0,1,0,1, 0,1,0,1, 0,1,0,1};

    const int bB = 18 * (tid & 0xF0) + (tid & 15);   // phase B: k at bB + 18k
    const int bC = tid + 2 * (tid >> 4);             // phase C: k at bC + 288k
    ulonglong2* st128 = reinterpret_cast<ulonglong2*>(st);

    ull a[16];
    __syncthreads();

    // ---- stage 2 (192 threads): build 16-entry kron diagonal tables, ---------
    // ---- OVERLAPPED with the layer-0 product-state compute            ---------
    if (tid < (NL - 1) * 3 * 16) {
        const int n  = tid & 15;
        const int lm = tid >> 4;            // 0..11
        const int lIdx = lm / 3, X = lm % 3;
        const int QB = 11 - 4 * X;          // QBASE of phase X
        float2 z2 = make_float2(1.f, 0.f), z1 = make_float2(1.f, 0.f);
        #pragma unroll
        for (int m = 0; m < 4; m++) {
            const int gi = lIdx * NQ + (QB - m);
            const int bit = (n >> m) & 1;
            float2 zb = Zb[gi]; if (!bit) zb.y = -zb.y;
            float2 za = Za[gi]; if (!bit) za.y = -za.y;
            z2 = cmul(z2, zb);
            z1 = cmul(z1, za);
        }
        d2tab[lm * 16 + n] = make_ulonglong2(pack2(z2.x, z2.x), pack2(-z2.y, z2.y));
        d1tab[lm * 16 + n] = make_ulonglong2(pack2(z1.x, z1.x), pack2(-z1.y, z1.y));
    }

    // layer 0: |0..0> -> product state, scatter-stored (post-perm layout)
    {
        float2 plow = make_float2(1.f, 0.f);
        #pragma unroll
        for (int p = 0; p < 8; p++) {                 // tid bit p <-> qubit 11-p
            float2 row = ((tid >> p) & 1) ? U10s[11 - p] : U00s[11 - p];
            plow = cmul(plow, row);
        }
        #pragma unroll
        for (int k = 0; k < 16; k++) {                // j = (k<<8) | tid
            float2 amp = plow;
            #pragma unroll
            for (int m = 0; m < 4; m++) {             // j bit 8+m <-> qubit 3-m
                float2 row = ((k >> m) & 1) ? U10s[3 - m] : U00s[3 - m];
                amp = cmul(amp, row);
            }
            int d = DSTK[k] ^ F_t;
            st[d + 2 * (d >> 4)] = pack2(amp.x, amp.y);
        }
    }
    __syncthreads();

    // ---------------- layers 1..4 ---------------------------------------------
    #pragma unroll 1
    for (int l = 1; l < NL; l++) {
        const int lIdx = l - 1;
        const ull* rotL = rot + lIdx * (NQ * 3);
        const ulonglong2* d2L = d2tab + lIdx * 3 * 16;
        const ulonglong2* d1L = d1tab + lIdx * 3 * 16;

        // phase A: thread-local contiguous rows, 128-bit accesses
        #pragma unroll
        for (int q = 0; q < 8; q++) {
            ulonglong2 v = st128[9 * tid + q];
            a[2 * q] = v.x; a[2 * q + 1] = v.y;
        }
        phase_euler<11>(a, rotL, d2L + 0 * 16, d1L + 0 * 16);  // qubits 11..8
        #pragma unroll
        for (int q = 0; q < 8; q++)
            st128[9 * tid + q] = make_ulonglong2(a[2 * q], a[2 * q + 1]);
        __syncwarp();                             // A->B exchange intra-half-warp

        // phase B
        #pragma unroll
        for (int k = 0; k < 16; k++) a[k] = st[bB + 18 * k];
        phase_euler<7>(a, rotL, d2L + 1 * 16, d1L + 1 * 16);   // qubits 7..4
        #pragma unroll
        for (int k = 0; k < 16; k++) st[bB + 18 * k] = a[k];
        __syncthreads();                          // B->C crosses warps

        // phase C (+ CNOT-ring scatter except last layer)
        #pragma unroll
        for (int k = 0; k < 16; k++) a[k] = st[bC + 288 * k];
        phase_euler<3>(a, rotL, d2L + 2 * 16, d1L + 2 * 16);   // qubits 3..0
        if (l != NL - 1) {
            #pragma unroll
            for (int k = 0; k < 16; k++) {
                int d = DSTK[k] ^ F_t;
                st[d + 2 * (d >> 4)] = a[k];
            }
            __syncthreads();
        }
    }

    // ---------------- measurement fused into last phase-C registers ------------
    float P0 = 0.f, P1 = 0.f, Q0 = 0.f, Q1 = 0.f;
    #pragma unroll
    for (int k = 0; k < 16; k++) {
        float2 v = *reinterpret_cast<float2*>(&a[k]);
        float pr = v.x * v.x + v.y * v.y;
        if (S01K[k]) P1 += pr; else P0 += pr;
        if (S23K[k]) Q1 += pr; else Q0 += pr;
    }
    float e01 = P0 - P1;
    if (par_t) e01 = -e01;
    float e23 = Q0 - Q1;

    #pragma unroll
    for (int off = 16; off > 0; off >>= 1) {
        e01 += __shfl_down_sync(0xffffffffu, e01, off);
        e23 += __shfl_down_sync(0xffffffffu, e23, off);
    }
    if ((tid & 31) == 0) { red0[tid >> 5] = e01; red1[tid >> 5] = e23; }
    __syncthreads();
    if (tid < 2) {
        const float* r = tid ? red1 : red0;
        float s = 0.f;
        #pragma unroll
        for (int w = 0; w < NT / 32; w++) s += r[w];
        out[b * 2 + tid] = ow[tid] * s;
    }
}

extern "C" void kernel_launch(void* const* d_in, const int* in_sizes, int n_in,
                              void* d_out, int out_size) {
    const float* x  = (const float*)d_in[0];   // (BATCH, 12)
    const float* iw = (const float*)d_in[1];   // (5, 12)
    const float* th = (const float*)d_in[2];   // (5, 12, 2)
    const float* ow = (const float*)d_in[3];   // (2,)
    float* out = (float*)d_out;                // (BATCH, 2)
    int batch = in_sizes[0] / NQ;
    qnet_kernel<<<batch, NT>>>(x, iw, th, ow, out);
}

// round 12
// speedup vs baseline: 1.3254x; 1.0804x over previous
#include <cuda_runtime.h>

#define NQ   12
#define DIM  4096
#define NL   5
#define NT   256
// pad-2 layout: loc(j) = j + 2*(j>>4) -> stride-18 rows, 16B-aligned rows
#define PAD_DIM (DIM + 2 * (DIM / 16))   // 4608 ull = 36 KB

typedef unsigned long long ull;

__device__ __forceinline__ ull f32x2_mul(ull a, ull b) {
    ull r;
    asm("mul.rn.f32x2 %0, %1, %2;" : "=l"(r) : "l"(a), "l"(b));
    return r;
}
__device__ __forceinline__ ull f32x2_fma(ull a, ull b, ull c) {
    ull r;
    asm("fma.rn.f32x2 %0, %1, %2, %3;" : "=l"(r) : "l"(a), "l"(b), "l"(c));
    return r;
}
__device__ __forceinline__ ull swap_halves(ull v) {
    uint2 t = *reinterpret_cast<uint2*>(&v);
    uint2 s = make_uint2(t.y, t.x);
    return *reinterpret_cast<ull*>(&s);
}
__device__ __forceinline__ ull pack2(float lo, float hi) {
    uint2 t = make_uint2(__float_as_uint(lo), __float_as_uint(hi));
    return *reinterpret_cast<ull*>(&t);
}
__device__ __forceinline__ float2 cmul(float2 a, float2 b) {
    return make_float2(a.x * b.x - a.y * b.y, a.x * b.y + a.y * b.x);
}

// diagonal apply from a 16-entry packed-dup table (indexed by register nibble)
__device__ __forceinline__ void diag_tab(ull a[16], const ulonglong2* __restrict__ t) {
    #pragma unroll
    for (int k = 0; k < 16; k++) {
        ulonglong2 e = t[k];
        ull r = f32x2_mul(e.x, a[k]);
        a[k] = f32x2_fma(e.y, swap_halves(a[k]), r);
    }
}
// diagonal apply of a single per-thread constant
__device__ __forceinline__ void diag_const(ull a[16], const ulonglong2 e) {
    #pragma unroll
    for (int k = 0; k < 16; k++) {
        ull r = f32x2_mul(e.x, a[k]);
        a[k] = f32x2_fma(e.y, swap_halves(a[k]), r);
    }
}
// 4 real rotations: register-nibble bit m <-> qubit QBASE-m; coeffs {c,s} packed
template <int QBASE>
__device__ __forceinline__ void rots4(ull a[16], const ulonglong2* __restrict__ rotL) {
    #pragma unroll
    for (int m = 0; m < 4; m++) {
        const ulonglong2 cs = rotL[QBASE - m];
        const ull c  = cs.x;
        const ull s  = cs.y;
        const ull ns = s ^ 0x8000000080000000ULL;   // -s via sign-bit flip
        #pragma unroll
        for (int k = 0; k < 16; k++) {
            if (!(k & (1 << m))) {
                ull s0 = a[k], s1 = a[k | (1 << m)];
                ull n0 = f32x2_mul(c, s0);
                n0 = f32x2_fma(ns, s1, n0);
                ull n1 = f32x2_mul(s, s0);
                n1 = f32x2_fma(c,  s1, n1);
                a[k] = n0; a[k | (1 << m)] = n1;
            }
        }
    }
}

// fused gate angles -> full 2x2 complex matrix entries (U = RZ(b)RY(a)RX(g))
__device__ __forceinline__ void fuse_gate(float g, float aa, float bb,
                                          float2& u00, float2& u01,
                                          float2& u10, float2& u11) {
    float sg, cg, sa, ca, sb, cb;
    __sincosf(g,  &sg, &cg);
    __sincosf(aa, &sa, &ca);
    __sincosf(bb, &sb, &cb);
    float cc = ca * cg, ss = sa * sg, sc = sa * cg, cs = ca * sg;
    float2 e0 = make_float2(cb, -sb);
    float2 e1 = make_float2(cb,  sb);
    u00 = cmul(e0, make_float2(cc,   ss));
    u01 = cmul(e0, make_float2(-sc, -cs));
    u10 = cmul(e1, make_float2(sc,  -cs));
    u11 = cmul(e1, make_float2(cc,  -ss));
}

__global__ void __launch_bounds__(NT, 4)
qnet_kernel(const float* __restrict__ x,
            const float* __restrict__ iw,
            const float* __restrict__ th,
            const float* __restrict__ ow,
            float* __restrict__ out) {
    __shared__ __align__(16) ull st[PAD_DIM];                      // 36 KB state
    __shared__ __align__(16) ulonglong2 d2tab[(NL - 1) * 3 * 16];  // 3 KB
    __shared__ __align__(16) ulonglong2 d1tab[(NL - 1) * 3 * 16];  // 3 KB
    __shared__ __align__(16) ulonglong2 rot[(NL - 1) * NQ];        // {c,s} packed
    __shared__ float2 Za[(NL - 1) * NQ], Zb[(NL - 1) * NQ];        // e^{ip}, e^{iq}
    __shared__ float2 U00s[NQ], U10s[NQ];                          // layer-0 col-0
    __shared__ float red0[NT / 32], red1[NT / 32];

    const int b   = blockIdx.x;
    const int tid = threadIdx.x;

    // ---- stage 1: per-gate build + SU(2) Euler decomposition (60 threads) ----
    if (tid < NL * NQ) {
        const int l = tid / NQ, q = tid % NQ;
        float xin = tanhf(x[b * NQ + q]);
        float g  = 0.5f * iw[l * NQ + q] * xin;
        float aa = 0.5f * th[(l * NQ + q) * 2 + 0];
        float bb = 0.5f * th[(l * NQ + q) * 2 + 1];
        float2 u00, u01, u10, u11;
        fuse_gate(g, aa, bb, u00, u01, u10, u11);
        if (l == 0) {
            U00s[q] = u00;
            U10s[q] = u10;
        } else {
            // U = D(2p) * R * D(2q2): cos = |u00|, sin = |u10|
            float tc = sqrtf(u00.x * u00.x + u00.y * u00.y);
            float ts = sqrtf(u10.x * u10.x + u10.y * u10.y);
            float A_ = -atan2f(u00.y, u00.x);
            float B_ =  atan2f(u10.y, u10.x);
            float p  = 0.5f * (A_ + B_);
            float q2 = 0.5f * (A_ - B_);
            const int gi = (l - 1) * NQ + q;
            rot[gi] = make_ulonglong2(pack2(tc, tc), pack2(ts, ts));
            float sp, cp, sq, cq;
            __sincosf(p,  &sp, &cp);
            __sincosf(q2, &sq, &cq);
            Za[gi] = make_float2(cp, sp);   // bit=1 entry; bit=0 is conj
            Zb[gi] = make_float2(cq, sq);
        }
    }

    // ---- CNOT-ring scatter map (inverse perm), GF(2)-linear closed form ----
    int gt = tid ^ (tid >> 1); gt ^= gt >> 2; gt ^= gt >> 4;
    const int par_t = gt & 1;
    const int F_t   = gt ^ (par_t << 11);
    const int DSTK[16] = {0x000, 0x9FF, 0xBFF, 0x200, 0xFFF, 0x600, 0x400, 0xDFF,
                          0x7FF, 0xE00, 0xC00, 0x5FF, 0x800, 0x1FF, 0x3FF, 0xA00};
    const bool S01K[16] = {0,1,1,0, 0,1,1,0, 1,0,0,1, 1,0,0,1};
    const bool S23K[16] = {0,1,0,1, 0,1,0,1, 0,1,0,1, 0,1,0,1};

    const int bB = 18 * (tid & 0xF0) + (tid & 15);   // phase B: k at bB + 18k
    const int bC = tid + 2 * (tid >> 4);             // phase C: k at bC + 288k
    ulonglong2* st128 = reinterpret_cast<ulonglong2*>(st);

    ull a[16];
    __syncthreads();

    // ---- stage 2 (192 threads): build 16-entry kron diagonal tables, ---------
    // ---- OVERLAPPED with the layer-0 product-state compute            ---------
    if (tid < (NL - 1) * 3 * 16) {
        const int n  = tid & 15;
        const int lm = tid >> 4;            // 0..11
        const int lIdx = lm / 3, X = lm % 3;
        const int QB = 11 - 4 * X;          // QBASE of phase X
        float2 z2 = make_float2(1.f, 0.f), z1 = make_float2(1.f, 0.f);
        #pragma unroll
        for (int m = 0; m < 4; m++) {
            const int gi = lIdx * NQ + (QB - m);
            const int bit = (n >> m) & 1;
            float2 zb = Zb[gi]; if (!bit) zb.y = -zb.y;
            float2 za = Za[gi]; if (!bit) za.y = -za.y;
            z2 = cmul(z2, zb);
            z1 = cmul(z1, za);
        }
        d2tab[lm * 16 + n] = make_ulonglong2(pack2(z2.x, z2.x), pack2(-z2.y, z2.y));
        d1tab[lm * 16 + n] = make_ulonglong2(pack2(z1.x, z1.x), pack2(-z1.y, z1.y));
    }

    // layer 0: |0..0> -> product state, scatter-stored (post-perm layout)
    {
        float2 plow = make_float2(1.f, 0.f);
        #pragma unroll
        for (int p = 0; p < 8; p++) {                 // tid bit p <-> qubit 11-p
            float2 row = ((tid >> p) & 1) ? U10s[11 - p] : U00s[11 - p];
            plow = cmul(plow, row);
        }
        #pragma unroll
        for (int k = 0; k < 16; k++) {                // j = (k<<8) | tid
            float2 amp = plow;
            #pragma unroll
            for (int m = 0; m < 4; m++) {             // j bit 8+m <-> qubit 3-m
                float2 row = ((k >> m) & 1) ? U10s[3 - m] : U00s[3 - m];
                amp = cmul(amp, row);
            }
            int d = DSTK[k] ^ F_t;
            st[d + 2 * (d >> 4)] = pack2(amp.x, amp.y);
        }
    }
    __syncthreads();

    // ---------------- layers 1..4 ---------------------------------------------
    // phase op = D1 * R * D2.  D1_A and D1_B are DEFERRED one phase (they are
    // per-thread constants there); D1_C of the last layer is dropped (|amp|^2).
    #pragma unroll 1
    for (int l = 1; l < NL; l++) {
        const int lIdx = l - 1;
        const ulonglong2* rotL = rot + lIdx * NQ;
        const ulonglong2* d2L = d2tab + lIdx * 3 * 16;
        const ulonglong2* d1L = d1tab + lIdx * 3 * 16;

        // phase A: thread-local contiguous rows, 128-bit accesses
        #pragma unroll
        for (int q = 0; q < 8; q++) {
            ulonglong2 v = st128[9 * tid + q];
            a[2 * q] = v.x; a[2 * q + 1] = v.y;
        }
        diag_tab(a, d2L + 0 * 16);
        rots4<11>(a, rotL);                       // qubits 11..8 (bits 0..3)
        #pragma unroll
        for (int q = 0; q < 8; q++)
            st128[9 * tid + q] = make_ulonglong2(a[2 * q], a[2 * q + 1]);
        __syncwarp();                             // A->B exchange intra-half-warp

        // phase B: apply deferred D1_A as per-thread constant (bits[3:0]=tid&15)
        #pragma unroll
        for (int k = 0; k < 16; k++) a[k] = st[bB + 18 * k];
        diag_const(a, d1L[0 * 16 + (tid & 15)]);
        diag_tab(a, d2L + 1 * 16);
        rots4<7>(a, rotL);                        // qubits 7..4 (bits 4..7)
        #pragma unroll
        for (int k = 0; k < 16; k++) st[bB + 18 * k] = a[k];
        __syncthreads();                          // B->C crosses warps

        // phase C: deferred D1_B const (bits[7:4]=(tid>>4)&15), then D2_C, rots,
        // then D1_C table (skipped on last layer), then CNOT-ring scatter
        #pragma unroll
        for (int k = 0; k < 16; k++) a[k] = st[bC + 288 * k];
        diag_const(a, d1L[1 * 16 + ((tid >> 4) & 15)]);
        diag_tab(a, d2L + 2 * 16);
        rots4<3>(a, rotL);                        // qubits 3..0 (bits 8..11)
        if (l != NL - 1) {
            diag_tab(a, d1L + 2 * 16);
            #pragma unroll
            for (int k = 0; k < 16; k++) {
                int d = DSTK[k] ^ F_t;
                st[d + 2 * (d >> 4)] = a[k];
            }
            __syncthreads();
        }
    }

    // ---------------- measurement fused into last phase-C registers ------------
    float P0 = 0.f, P1 = 0.f, Q0 = 0.f, Q1 = 0.f;
    #pragma unroll
    for (int k = 0; k < 16; k++) {
        float2 v = *reinterpret_cast<float2*>(&a[k]);
        float pr = v.x * v.x + v.y * v.y;
        if (S01K[k]) P1 += pr; else P0 += pr;
        if (S23K[k]) Q1 += pr; else Q0 += pr;
    }
    float e01 = P0 - P1;
    if (par_t) e01 = -e01;
    float e23 = Q0 - Q1;

    #pragma unroll
    for (int off = 16; off > 0; off >>= 1) {
        e01 += __shfl_down_sync(0xffffffffu, e01, off);
        e23 += __shfl_down_sync(0xffffffffu, e23, off);
    }
    if ((tid & 31) == 0) { red0[tid >> 5] = e01; red1[tid >> 5] = e23; }
    __syncthreads();
    if (tid < 2) {
        const float* r = tid ? red1 : red0;
        float s = 0.f;
        #pragma unroll
        for (int w = 0; w < NT / 32; w++) s += r[w];
        out[b * 2 + tid] = ow[tid] * s;
    }
}

extern "C" void kernel_launch(void* const* d_in, const int* in_sizes, int n_in,
                              void* d_out, int out_size) {
    const float* x  = (const float*)d_in[0];   // (BATCH, 12)
    const float* iw = (const float*)d_in[1];   // (5, 12)
    const float* th = (const float*)d_in[2];   // (5, 12, 2)
    const float* ow = (const float*)d_in[3];   // (2,)
    float* out = (float*)d_out;                // (BATCH, 2)
    int batch = in_sizes[0] / NQ;
    qnet_kernel<<<batch, NT>>>(x, iw, th, ow, out);
}

// round 13
// speedup vs baseline: 1.4786x; 1.1156x over previous
#include <cuda_runtime.h>

#define NQ   12
#define DIM  4096
#define NL   5
#define NT   256
// pad-2 layout: loc(j) = j + 2*(j>>4) -> stride-18 rows, 16B-aligned rows
#define PAD_DIM (DIM + 2 * (DIM / 16))   // 4608 ull = 36 KB

typedef unsigned long long ull;

__device__ __forceinline__ ull f32x2_mul(ull a, ull b) {
    ull r;
    asm("mul.rn.f32x2 %0, %1, %2;" : "=l"(r) : "l"(a), "l"(b));
    return r;
}
__device__ __forceinline__ ull f32x2_fma(ull a, ull b, ull c) {
    ull r;
    asm("fma.rn.f32x2 %0, %1, %2, %3;" : "=l"(r) : "l"(a), "l"(b), "l"(c));
    return r;
}
__device__ __forceinline__ ull swap_halves(ull v) {
    uint2 t = *reinterpret_cast<uint2*>(&v);
    uint2 s = make_uint2(t.y, t.x);
    return *reinterpret_cast<ull*>(&s);
}
__device__ __forceinline__ ull pack2(float lo, float hi) {
    uint2 t = make_uint2(__float_as_uint(lo), __float_as_uint(hi));
    return *reinterpret_cast<ull*>(&t);
}
__device__ __forceinline__ float2 cmul(float2 a, float2 b) {
    return make_float2(a.x * b.x - a.y * b.y, a.x * b.y + a.y * b.x);
}
__device__ __forceinline__ ulonglong2 packdup(float2 z) {
    return make_ulonglong2(pack2(z.x, z.x), pack2(-z.y, z.y));
}

// diagonal apply from a 16-entry packed-dup table (indexed by register nibble)
__device__ __forceinline__ void diag_tab(ull a[16], const ulonglong2* __restrict__ t) {
    #pragma unroll
    for (int k = 0; k < 16; k++) {
        ulonglong2 e = t[k];
        ull r = f32x2_mul(e.x, a[k]);
        a[k] = f32x2_fma(e.y, swap_halves(a[k]), r);
    }
}
// diagonal apply of a single per-thread constant
__device__ __forceinline__ void diag_const(ull a[16], const ulonglong2 e) {
    #pragma unroll
    for (int k = 0; k < 16; k++) {
        ull r = f32x2_mul(e.x, a[k]);
        a[k] = f32x2_fma(e.y, swap_halves(a[k]), r);
    }
}
// 4 real rotations: register-nibble bit m <-> qubit QBASE-m; coeffs {c,s} packed
template <int QBASE>
__device__ __forceinline__ void rots4(ull a[16], const ulonglong2* __restrict__ rotL) {
    #pragma unroll
    for (int m = 0; m < 4; m++) {
        const ulonglong2 cs = rotL[QBASE - m];
        const ull c  = cs.x;
        const ull s  = cs.y;
        const ull ns = s ^ 0x8000000080000000ULL;   // -s via sign-bit flip
        #pragma unroll
        for (int k = 0; k < 16; k++) {
            if (!(k & (1 << m))) {
                ull s0 = a[k], s1 = a[k | (1 << m)];
                ull n0 = f32x2_mul(c, s0);
                n0 = f32x2_fma(ns, s1, n0);
                ull n1 = f32x2_mul(s, s0);
                n1 = f32x2_fma(c,  s1, n1);
                a[k] = n0; a[k | (1 << m)] = n1;
            }
        }
    }
}

// fused gate angles -> full 2x2 complex matrix entries (U = RZ(b)RY(a)RX(g))
__device__ __forceinline__ void fuse_gate(float g, float aa, float bb,
                                          float2& u00, float2& u01,
                                          float2& u10, float2& u11) {
    float sg, cg, sa, ca, sb, cb;
    __sincosf(g,  &sg, &cg);
    __sincosf(aa, &sa, &ca);
    __sincosf(bb, &sb, &cb);
    float cc = ca * cg, ss = sa * sg, sc = sa * cg, cs = ca * sg;
    float2 e0 = make_float2(cb, -sb);
    float2 e1 = make_float2(cb,  sb);
    u00 = cmul(e0, make_float2(cc,   ss));
    u01 = cmul(e0, make_float2(-sc, -cs));
    u10 = cmul(e1, make_float2(sc,  -cs));
    u11 = cmul(e1, make_float2(cc,  -ss));
}

__global__ void __launch_bounds__(NT, 4)
qnet_kernel(const float* __restrict__ x,
            const float* __restrict__ iw,
            const float* __restrict__ th,
            const float* __restrict__ ow,
            float* __restrict__ out) {
    __shared__ __align__(16) ull st[PAD_DIM];                    // 36 KB state
    __shared__ __align__(16) ulonglong2 d2Atab[(NL - 1) * 16];   // phase-A D2 tables
    __shared__ __align__(16) ulonglong2 d1Ctab[(NL - 1) * 16];   // phase-C D1 tables
    __shared__ float2 cAf[(NL - 1) * 16];    // D2_B entries  (const in phase A)
    __shared__ float2 cB1f[(NL - 1) * 16];   // D1_A entries  (const in phase B)
    __shared__ float2 cB2f[(NL - 1) * 16];   // D2_C entries  (const in phase B)
    __shared__ float2 cCf[(NL - 1) * 16];    // D1_B entries  (const in phase C)
    __shared__ __align__(16) ulonglong2 rot[(NL - 1) * NQ];      // {c,s} packed
    __shared__ float2 Za[(NL - 1) * NQ], Zb[(NL - 1) * NQ];      // e^{ip}, e^{iq}
    __shared__ float2 U00s[NQ], U10s[NQ];                        // layer-0 col-0
    __shared__ float red0[NT / 32], red1[NT / 32];

    const int b   = blockIdx.x;
    const int tid = threadIdx.x;

    // ---- stage 1: per-gate build + SU(2) Euler decomposition (60 threads) ----
    if (tid < NL * NQ) {
        const int l = tid / NQ, q = tid % NQ;
        float xin = tanhf(x[b * NQ + q]);
        float g  = 0.5f * iw[l * NQ + q] * xin;
        float aa = 0.5f * th[(l * NQ + q) * 2 + 0];
        float bb = 0.5f * th[(l * NQ + q) * 2 + 1];
        float2 u00, u01, u10, u11;
        fuse_gate(g, aa, bb, u00, u01, u10, u11);
        if (l == 0) {
            U00s[q] = u00;
            U10s[q] = u10;
        } else {
            float tc = sqrtf(u00.x * u00.x + u00.y * u00.y);
            float ts = sqrtf(u10.x * u10.x + u10.y * u10.y);
            float A_ = -atan2f(u00.y, u00.x);
            float B_ =  atan2f(u10.y, u10.x);
            float p  = 0.5f * (A_ + B_);
            float q2 = 0.5f * (A_ - B_);
            const int gi = (l - 1) * NQ + q;
            rot[gi] = make_ulonglong2(pack2(tc, tc), pack2(ts, ts));
            float sp, cp, sq, cq;
            __sincosf(p,  &sp, &cp);
            __sincosf(q2, &sq, &cq);
            Za[gi] = make_float2(cp, sp);   // bit=1 entry; bit=0 is conj
            Zb[gi] = make_float2(cq, sq);
        }
    }

    // ---- CNOT-ring scatter map (inverse perm), GF(2)-linear closed form ----
    int gt = tid ^ (tid >> 1); gt ^= gt >> 2; gt ^= gt >> 4;
    const int par_t = gt & 1;
    const int F_t   = gt ^ (par_t << 11);
    const int DSTK[16] = {0x000, 0x9FF, 0xBFF, 0x200, 0xFFF, 0x600, 0x400, 0xDFF,
                          0x7FF, 0xE00, 0xC00, 0x5FF, 0x800, 0x1FF, 0x3FF, 0xA00};
    const bool S01K[16] = {0,1,1,0, 0,1,1,0, 1,0,0,1, 1,0,0,1};
    const bool S23K[16] = {0,1,0,1, 0,1,0,1, 0,1,0,1, 0,1,0,1};

    const int bB = 18 * (tid & 0xF0) + (tid & 15);   // phase B: k at bB + 18k
    const int bC = tid + 2 * (tid >> 4);             // phase C: k at bC + 288k
    ulonglong2* st128 = reinterpret_cast<ulonglong2*>(st);

    ull a[16];
    __syncthreads();

    // ---- stage 2 (192 threads): kron diagonal products, routed to their ------
    // ---- application site; OVERLAPPED with layer-0 product-state compute ------
    if (tid < (NL - 1) * 3 * 16) {
        const int n  = tid & 15;
        const int lm = tid >> 4;            // 0..11
        const int lIdx = lm / 3, X = lm % 3;
        const int QB = 11 - 4 * X;          // QBASE of phase X
        float2 z2 = make_float2(1.f, 0.f), z1 = make_float2(1.f, 0.f);
        #pragma unroll
        for (int m = 0; m < 4; m++) {
            const int gi = lIdx * NQ + (QB - m);
            const int bit = (n >> m) & 1;
            float2 zb = Zb[gi]; if (!bit) zb.y = -zb.y;
            float2 za = Za[gi]; if (!bit) za.y = -za.y;
            z2 = cmul(z2, zb);
            z1 = cmul(z1, za);
        }
        if (X == 0) {        // phase A: D2 stays a table, D1 -> const in phase B
            d2Atab[lIdx * 16 + n] = packdup(z2);
            cB1f[lIdx * 16 + n]   = z1;
        } else if (X == 1) { // phase B: D2 -> const in phase A, D1 -> const in C
            cAf[lIdx * 16 + n] = z2;
            cCf[lIdx * 16 + n] = z1;
        } else {             // phase C: D2 -> const in phase B, D1 stays a table
            cB2f[lIdx * 16 + n]   = z2;
            d1Ctab[lIdx * 16 + n] = packdup(z1);
        }
    }

    // layer 0: |0..0> -> product state, scatter-stored (post-perm layout)
    {
        float2 plow = make_float2(1.f, 0.f);
        #pragma unroll
        for (int p = 0; p < 8; p++) {                 // tid bit p <-> qubit 11-p
            float2 row = ((tid >> p) & 1) ? U10s[11 - p] : U00s[11 - p];
            plow = cmul(plow, row);
        }
        #pragma unroll
        for (int k = 0; k < 16; k++) {                // j = (k<<8) | tid
            float2 amp = plow;
            #pragma unroll
            for (int m = 0; m < 4; m++) {             // j bit 8+m <-> qubit 3-m
                float2 row = ((k >> m) & 1) ? U10s[3 - m] : U00s[3 - m];
                amp = cmul(amp, row);
            }
            int d = DSTK[k] ^ F_t;
            st[d + 2 * (d >> 4)] = pack2(amp.x, amp.y);
        }
    }
    __syncthreads();

    // ---------------- layers 1..3 (full: D1s applied) --------------------------
    #pragma unroll 1
    for (int lIdx = 0; lIdx < NL - 2; lIdx++) {
        const ulonglong2* rotL = rot + lIdx * NQ;

        // phase A: D2_A table, rots(11..8), then D2_B as per-thread const
        #pragma unroll
        for (int q = 0; q < 8; q++) {
            ulonglong2 v = st128[9 * tid + q];
            a[2 * q] = v.x; a[2 * q + 1] = v.y;
        }
        diag_tab(a, d2Atab + lIdx * 16);
        rots4<11>(a, rotL);
        diag_const(a, packdup(cAf[lIdx * 16 + (tid & 15)]));
        #pragma unroll
        for (int q = 0; q < 8; q++)
            st128[9 * tid + q] = make_ulonglong2(a[2 * q], a[2 * q + 1]);
        __syncwarp();

        // phase B: merged (D1_A * D2_C) const, rots(7..4)
        #pragma unroll
        for (int k = 0; k < 16; k++) a[k] = st[bB + 18 * k];
        {
            float2 zm = cmul(cB1f[lIdx * 16 + (tid & 15)],
                             cB2f[lIdx * 16 + (tid >> 4)]);
            diag_const(a, packdup(zm));
        }
        rots4<7>(a, rotL);
        #pragma unroll
        for (int k = 0; k < 16; k++) st[bB + 18 * k] = a[k];
        __syncthreads();

        // phase C: D1_B const, rots(3..0), D1_C table, CNOT-ring scatter
        #pragma unroll
        for (int k = 0; k < 16; k++) a[k] = st[bC + 288 * k];
        diag_const(a, packdup(cCf[lIdx * 16 + (tid >> 4)]));
        rots4<3>(a, rotL);
        diag_tab(a, d1Ctab + lIdx * 16);
        #pragma unroll
        for (int k = 0; k < 16; k++) {
            int d = DSTK[k] ^ F_t;
            st[d + 2 * (d >> 4)] = a[k];
        }
        __syncthreads();
    }

    // ---------------- last layer: all D1 diagonals dropped (|amp|^2) -----------
    {
        const int lIdx = NL - 2;
        const ulonglong2* rotL = rot + lIdx * NQ;

        #pragma unroll
        for (int q = 0; q < 8; q++) {
            ulonglong2 v = st128[9 * tid + q];
            a[2 * q] = v.x; a[2 * q + 1] = v.y;
        }
        diag_tab(a, d2Atab + lIdx * 16);
        rots4<11>(a, rotL);
        diag_const(a, packdup(cAf[lIdx * 16 + (tid & 15)]));
        #pragma unroll
        for (int q = 0; q < 8; q++)
            st128[9 * tid + q] = make_ulonglong2(a[2 * q], a[2 * q + 1]);
        __syncwarp();

        #pragma unroll
        for (int k = 0; k < 16; k++) a[k] = st[bB + 18 * k];
        diag_const(a, packdup(cB2f[lIdx * 16 + (tid >> 4)]));   // D2_C only
        rots4<7>(a, rotL);
        #pragma unroll
        for (int k = 0; k < 16; k++) st[bB + 18 * k] = a[k];
        __syncthreads();

        #pragma unroll
        for (int k = 0; k < 16; k++) a[k] = st[bC + 288 * k];
        rots4<3>(a, rotL);          // no D1_B, no D1_C, no scatter
    }

    // ---------------- measurement fused into last phase-C registers ------------
    float P0 = 0.f, P1 = 0.f, Q0 = 0.f, Q1 = 0.f;
    #pragma unroll
    for (int k = 0; k < 16; k++) {
        float2 v = *reinterpret_cast<float2*>(&a[k]);
        float pr = v.x * v.x + v.y * v.y;
        if (S01K[k]) P1 += pr; else P0 += pr;
        if (S23K[k]) Q1 += pr; else Q0 += pr;
    }
    float e01 = P0 - P1;
    if (par_t) e01 = -e01;
    float e23 = Q0 - Q1;

    #pragma unroll
    for (int off = 16; off > 0; off >>= 1) {
        e01 += __shfl_down_sync(0xffffffffu, e01, off);
        e23 += __shfl_down_sync(0xffffffffu, e23, off);
    }
    if ((tid & 31) == 0) { red0[tid >> 5] = e01; red1[tid >> 5] = e23; }
    __syncthreads();
    if (tid < 2) {
        const float* r = tid ? red1 : red0;
        float s = 0.f;
        #pragma unroll
        for (int w = 0; w < NT / 32; w++) s += r[w];
        out[b * 2 + tid] = ow[tid] * s;
    }
}

extern "C" void kernel_launch(void* const* d_in, const int* in_sizes, int n_in,
                              void* d_out, int out_size) {
    const float* x  = (const float*)d_in[0];   // (BATCH, 12)
    const float* iw = (const float*)d_in[1];   // (5, 12)
    const float* th = (const float*)d_in[2];   // (5, 12, 2)
    const float* ow = (const float*)d_in[3];   // (2,)
    float* out = (float*)d_out;                // (BATCH, 2)
    int batch = in_sizes[0] / NQ;
    qnet_kernel<<<batch, NT>>>(x, iw, th, ow, out);
}